// round 7
// baseline (speedup 1.0000x reference)
#include <cuda_runtime.h>
#include <cuda_bf16.h>
#include <math.h>

#define NN 100000
#define EE 3200000
#define NEMAX (EE + NN + 8 * NN)   // padded CSR (segments rounded up to 8)
#define GEMMB 391          // ceil(NN/256) gemm blocks (256 rows each)
#define CNTB 256           // count blocks fused into k1
#define PADT 260           // padded row length of transposed x tile (even!)

typedef unsigned long long ull;

// ---------------- scratch (device globals; no allocation allowed) ----------
__device__ __align__(16) float g_xp1[NN * 32];   // x @ W1
__device__ float g_as1[NN * 4];
__device__ float g_ad1[NN * 4];
__device__ __align__(16) float g_xp2[NN * 8];    // h @ W2
__device__ float g_as2[NN];
__device__ float g_ad2[NN];
__device__ int   g_deg[NN];        // zero-init; reset to 0 by alloc each run
__device__ int   g_degN[NN];       // real degree incl self-loop
__device__ int   g_off[NN];
__device__ int   g_pos[NN];
__device__ __align__(8) int g_csr[NEMAX];
__device__ int   g_total;          // zero-init; reset to 0 by scatter each run

// ---------------- packed f32x2 helpers ------------------------------------
__device__ __forceinline__ ull dup2(float v) {
    ull r; unsigned u = __float_as_uint(v);
    asm("mov.b64 %0, {%1, %1};" : "=l"(r) : "r"(u));
    return r;
}
__device__ __forceinline__ ull fma2(ull a, ull b, ull c) {
    ull d;
    asm("fma.rn.f32x2 %0, %1, %2, %3;" : "=l"(d) : "l"(a), "l"(b), "l"(c));
    return d;
}
__device__ __forceinline__ void unpack2(ull v, float& lo, float& hi) {
    unsigned a, b;
    asm("mov.b64 {%0, %1}, %2;" : "=r"(a), "=r"(b) : "l"(v));
    lo = __uint_as_float(a); hi = __uint_as_float(b);
}

// ============ K1: fused [GEMM1 + attn1 epilogue] & [degree count] ==========
__global__ __launch_bounds__(256) void k1_gemm_count(
    const float* __restrict__ x, const float* __restrict__ W,
    const float* __restrict__ as1, const float* __restrict__ ad1,
    const int* __restrict__ dst, int E)
{
    if (blockIdx.x >= GEMMB) {                 // ---- count blocks ----
        int i = (blockIdx.x - GEMMB) * 256 + threadIdx.x;
        for (; i < E; i += CNTB * 256) atomicAdd(&g_deg[dst[i]], 1);
        return;
    }
    __shared__ float xs[32 * PADT];            // [k][row] transposed
    __shared__ float ws[32 * 32];              // [k][col]
    int t = threadIdx.x;
    int row0 = blockIdx.x * 256;
    int rg  = t >> 3;                          // 0..31 -> rows rg*8..rg*8+7
    int cg4 = (t & 7) << 2;                    // 0,4,...,28 col base

    ull acc[4][4];
#pragma unroll
    for (int p = 0; p < 4; p++)
#pragma unroll
        for (int c = 0; c < 4; c++) acc[p][c] = 0ull;

    for (int kk = 0; kk < 512; kk += 32) {
#pragma unroll
        for (int i = 0; i < 8; i++) {
            int lf  = i * 256 + t;
            int row = lf >> 3;
            int k4  = (lf & 7) << 2;
            float4 v = make_float4(0.f, 0.f, 0.f, 0.f);
            int grow = row0 + row;
            if (grow < NN)
                v = *(const float4*)(x + (size_t)grow * 512 + kk + k4);
            xs[(k4 + 0) * PADT + row] = v.x;
            xs[(k4 + 1) * PADT + row] = v.y;
            xs[(k4 + 2) * PADT + row] = v.z;
            xs[(k4 + 3) * PADT + row] = v.w;
        }
        {
            int r = t >> 3, k4 = (t & 7) << 2;
            *(float4*)&ws[r * 32 + k4] = *(const float4*)(W + (size_t)(kk + r) * 32 + k4);
        }
        __syncthreads();
#pragma unroll
        for (int k = 0; k < 32; k++) {
            float4 wv = *(float4*)&ws[k * 32 + cg4];
            ull w0 = dup2(wv.x), w1 = dup2(wv.y), w2 = dup2(wv.z), w3 = dup2(wv.w);
            const ull* xr = (const ull*)&xs[k * PADT + (rg << 3)];
            ull x0 = xr[0], x1 = xr[1], x2 = xr[2], x3 = xr[3];
            acc[0][0] = fma2(x0, w0, acc[0][0]); acc[0][1] = fma2(x0, w1, acc[0][1]);
            acc[0][2] = fma2(x0, w2, acc[0][2]); acc[0][3] = fma2(x0, w3, acc[0][3]);
            acc[1][0] = fma2(x1, w0, acc[1][0]); acc[1][1] = fma2(x1, w1, acc[1][1]);
            acc[1][2] = fma2(x1, w2, acc[1][2]); acc[1][3] = fma2(x1, w3, acc[1][3]);
            acc[2][0] = fma2(x2, w0, acc[2][0]); acc[2][1] = fma2(x2, w1, acc[2][1]);
            acc[2][2] = fma2(x2, w2, acc[2][2]); acc[2][3] = fma2(x2, w3, acc[2][3]);
            acc[3][0] = fma2(x3, w0, acc[3][0]); acc[3][1] = fma2(x3, w1, acc[3][1]);
            acc[3][2] = fma2(x3, w2, acc[3][2]); acc[3][3] = fma2(x3, w3, acc[3][3]);
        }
        __syncthreads();
    }

    int head = cg4 >> 3;
    int half = (cg4 >> 2) & 1;
    float a_s[4], a_d[4];
#pragma unroll
    for (int c = 0; c < 4; c++) {
        a_s[c] = as1[head * 8 + half * 4 + c];
        a_d[c] = ad1[head * 8 + half * 4 + c];
    }
#pragma unroll
    for (int p = 0; p < 4; p++) {
        float o0[4], o1[4];
#pragma unroll
        for (int c = 0; c < 4; c++) unpack2(acc[p][c], o0[c], o1[c]);
#pragma unroll
        for (int rr = 0; rr < 2; rr++) {
            float* o = rr ? o1 : o0;
            int row = row0 + (rg << 3) + (p << 1) + rr;
            float sv = o[0]*a_s[0] + o[1]*a_s[1] + o[2]*a_s[2] + o[3]*a_s[3];
            float dv = o[0]*a_d[0] + o[1]*a_d[1] + o[2]*a_d[2] + o[3]*a_d[3];
            sv += __shfl_xor_sync(0xffffffffu, sv, 1);
            dv += __shfl_xor_sync(0xffffffffu, dv, 1);
            if (row < NN) {
                *(float4*)(g_xp1 + (size_t)row * 32 + cg4) =
                    make_float4(o[0], o[1], o[2], o[3]);
                if (half == 0) g_as1[row * 4 + head] = sv;
                else           g_ad1[row * 4 + head] = dv;
            }
        }
    }
}

// ------ CSR alloc: pad each segment to multiple of 8, reset g_deg ----------
__global__ void alloc_kernel() {
    int n = blockIdx.x * blockDim.x + threadIdx.x;
    int lane = threadIdx.x & 31;
    int deg = (n < NN) ? g_deg[n] + 1 : 0;     // +1 self-loop
    int degP = (deg + 7) & ~7;                 // padded
    int scan = degP;
#pragma unroll
    for (int d = 1; d < 32; d <<= 1) {
        int tv = __shfl_up_sync(0xffffffffu, scan, d);
        if (lane >= d) scan += tv;
    }
    int total = __shfl_sync(0xffffffffu, scan, 31);
    int base = 0;
    if (lane == 31) base = atomicAdd(&g_total, total);
    base = __shfl_sync(0xffffffffu, base, 31);
    int off = base + scan - degP;
    if (n < NN) {
        g_off[n]  = off;
        g_csr[off] = n;                        // self-loop in slot 0
        g_pos[n]  = off + 1;
        g_degN[n] = deg;
        for (int i = deg; i < degP; i++) g_csr[off + i] = n;  // pads (p = 0)
        g_deg[n]  = 0;                          // ready for next replay
    }
}

__global__ void scatter_kernel(const int* __restrict__ src,
                               const int* __restrict__ dst, int E) {
    if (blockIdx.x == 0 && threadIdx.x == 0) g_total = 0;
    int i = blockIdx.x * blockDim.x + threadIdx.x;
    if (i >= E) return;
    int d = dst[i];
    int slot = atomicAdd(&g_pos[d], 1);
    g_csr[slot] = src[i];
}

// == l1: zero-shuffle hot loop, dual chains, fused ELU + xp2/as2/ad2 ========
__global__ __launch_bounds__(256) void l1_kernel(
    const float* __restrict__ b1, const float* __restrict__ W2,
    const float* __restrict__ as2v, const float* __restrict__ ad2v)
{
    __shared__ float W2s[256];
    __shared__ float hs[8][36];
    int t = threadIdx.x;
    W2s[t] = W2[t];
    __syncthreads();

    int wid = t >> 5, lane = t & 31;
    int n = blockIdx.x * 8 + wid;              // grid 12500*8 == NN exactly
    int off = g_off[n], deg = g_degN[n];
    int degP = (deg + 7) & ~7;
    int q  = lane >> 3;                        // edge-pair group 0..3
    int c4 = lane & 7;                         // channel quad (head = c4>>1)
    int hc = c4 >> 1;
    float adh = g_ad1[n * 4 + hc];
    const float* xp1q = g_xp1 + (c4 << 2);
    const int* csrp = g_csr + off + (q << 1);

    float4 acc = make_float4(0.f, 0.f, 0.f, 0.f);
    float sum = 0.f;
#pragma unroll 2
    for (int base = 0; base < degP; base += 8) {
        int2 s2 = *(const int2*)(csrp + base);  // edges 2q, 2q+1 (8-dup)
        float vA = g_as1[s2.x * 4 + hc] + adh;
        float vB = g_as1[s2.y * 4 + hc] + adh;
        vA = fmaxf(vA, 0.2f * vA);              // leaky relu
        vB = fmaxf(vB, 0.2f * vB);
        int e0 = base + (q << 1);
        float pA = (e0     < deg) ? __expf(vA) : 0.f;
        float pB = (e0 + 1 < deg) ? __expf(vB) : 0.f;
        sum += pA + pB;
        float4 xa = *(const float4*)(xp1q + (size_t)s2.x * 32);
        float4 xb = *(const float4*)(xp1q + (size_t)s2.y * 32);
        acc.x = fmaf(pA, xa.x, fmaf(pB, xb.x, acc.x));
        acc.y = fmaf(pA, xa.y, fmaf(pB, xb.y, acc.y));
        acc.z = fmaf(pA, xa.z, fmaf(pB, xb.z, acc.z));
        acc.w = fmaf(pA, xa.w, fmaf(pB, xb.w, acc.w));
    }
    // reduce over edge-pair groups q (bits 3,4); sum lands per-head in-lane
    sum   += __shfl_xor_sync(0xffffffffu, sum, 8);
    acc.x += __shfl_xor_sync(0xffffffffu, acc.x, 8);
    acc.y += __shfl_xor_sync(0xffffffffu, acc.y, 8);
    acc.z += __shfl_xor_sync(0xffffffffu, acc.z, 8);
    acc.w += __shfl_xor_sync(0xffffffffu, acc.w, 8);
    sum   += __shfl_xor_sync(0xffffffffu, sum, 16);
    acc.x += __shfl_xor_sync(0xffffffffu, acc.x, 16);
    acc.y += __shfl_xor_sync(0xffffffffu, acc.y, 16);
    acc.z += __shfl_xor_sync(0xffffffffu, acc.z, 16);
    acc.w += __shfl_xor_sync(0xffffffffu, acc.w, 16);
    float invd = 1.f / sum;                     // already per-head, in-lane

    if (q == 0) {                               // lanes 0..7 hold all quads
        float4 bv = *(const float4*)(b1 + (c4 << 2));
        float o0 = fmaf(acc.x, invd, bv.x);
        float o1 = fmaf(acc.y, invd, bv.y);
        float o2 = fmaf(acc.z, invd, bv.z);
        float o3 = fmaf(acc.w, invd, bv.w);
        o0 = o0 > 0.f ? o0 : expm1f(o0);
        o1 = o1 > 0.f ? o1 : expm1f(o1);
        o2 = o2 > 0.f ? o2 : expm1f(o2);
        o3 = o3 > 0.f ? o3 : expm1f(o3);
        *(float4*)&hs[wid][c4 << 2] = make_float4(o0, o1, o2, o3);
    }
    __syncwarp();

    // fused xp2 = h @ W2, plus as2/ad2
    if (lane < 8) {
        float s2 = 0.f;
#pragma unroll
        for (int k2 = 0; k2 < 32; k2++)
            s2 = fmaf(hs[wid][k2], W2s[k2 * 8 + lane], s2);
        g_xp2[(size_t)n * 8 + lane] = s2;
        float a = s2 * as2v[lane], d = s2 * ad2v[lane];
        a += __shfl_xor_sync(0xffu, a, 1);
        a += __shfl_xor_sync(0xffu, a, 2);
        a += __shfl_xor_sync(0xffu, a, 4);
        d += __shfl_xor_sync(0xffu, d, 1);
        d += __shfl_xor_sync(0xffu, d, 2);
        d += __shfl_xor_sync(0xffu, d, 4);
        if (lane == 0) { g_as2[n] = a; g_ad2[n] = d; }
    }
}

// ========== l2: zero-shuffle hot loop, float2 gathers ======================
__global__ __launch_bounds__(256) void l2_kernel(float* __restrict__ out,
                                                 const float* __restrict__ b2)
{
    int t = threadIdx.x, wid = t >> 5, lane = t & 31;
    int n = blockIdx.x * 8 + wid;
    int off = g_off[n], deg = g_degN[n];
    int degP = (deg + 7) & ~7;
    int j8 = lane >> 2, c2 = lane & 3;          // edge j8, channel-pair c2
    float adn = g_ad2[n];
    const float* xp2p = g_xp2 + (c2 << 1);

    float2 acc = make_float2(0.f, 0.f);
    float sum = 0.f;
#pragma unroll 2
    for (int base = 0; base < degP; base += 8) {
        int sv = g_csr[off + base + j8];         // 8 distinct, 4-way dup
        float v = g_as2[sv] + adn;
        v = fmaxf(v, 0.2f * v);
        float p = (base + j8 < deg) ? __expf(v) : 0.f;
        sum += p;                                 // each edge once per lane-row
        float2 xv = *(const float2*)(xp2p + (size_t)sv * 8);
        acc.x = fmaf(p, xv.x, acc.x);
        acc.y = fmaf(p, xv.y, acc.y);
    }
    // reduce over edge lanes j8 (bits 2,3,4)
    sum   += __shfl_xor_sync(0xffffffffu, sum, 4);
    acc.x += __shfl_xor_sync(0xffffffffu, acc.x, 4);
    acc.y += __shfl_xor_sync(0xffffffffu, acc.y, 4);
    sum   += __shfl_xor_sync(0xffffffffu, sum, 8);
    acc.x += __shfl_xor_sync(0xffffffffu, acc.x, 8);
    acc.y += __shfl_xor_sync(0xffffffffu, acc.y, 8);
    sum   += __shfl_xor_sync(0xffffffffu, sum, 16);
    acc.x += __shfl_xor_sync(0xffffffffu, acc.x, 16);
    acc.y += __shfl_xor_sync(0xffffffffu, acc.y, 16);
    float invd = 1.f / sum;
    if (lane < 4) {
        float2 bv = *(const float2*)(b2 + (c2 << 1));
        float2 ov;
        ov.x = fmaf(acc.x, invd, bv.x);
        ov.y = fmaf(acc.y, invd, bv.y);
        *(float2*)(out + (size_t)n * 8 + (c2 << 1)) = ov;
    }
}

// ---------------------------------------------------------------------------
extern "C" void kernel_launch(void* const* d_in, const int* in_sizes, int n_in,
                              void* d_out, int out_size) {
    const float* x        = (const float*)d_in[0];
    const int*   eidx     = (const int*)d_in[1];
    const float* W1       = (const float*)d_in[2];
    const float* att_src1 = (const float*)d_in[3];
    const float* att_dst1 = (const float*)d_in[4];
    const float* b1       = (const float*)d_in[5];
    const float* W2       = (const float*)d_in[6];
    const float* att_src2 = (const float*)d_in[7];
    const float* att_dst2 = (const float*)d_in[8];
    const float* b2       = (const float*)d_in[9];
    float* out = (float*)d_out;

    int E = in_sizes[1] / 2;
    const int* src = eidx;
    const int* dst = eidx + E;

    k1_gemm_count<<<GEMMB + CNTB, 256>>>(x, W1, att_src1, att_dst1, dst, E);
    alloc_kernel<<<(NN + 255) / 256, 256>>>();
    scatter_kernel<<<(E + 255) / 256, 256>>>(src, dst, E);
    l1_kernel<<<NN / 8, 256>>>(b1, W2, att_src2, att_dst2);
    l2_kernel<<<NN / 8, 256>>>(out, b2);
}

// round 8
// speedup vs baseline: 1.1111x; 1.1111x over previous
#include <cuda_runtime.h>
#include <cuda_bf16.h>
#include <math.h>

#define NN 100000
#define EE 3200000
#define NEMAX (EE + NN + 8 * NN)   // padded CSR (segments rounded up to 8)
#define GEMMB 391          // ceil(NN/256) gemm blocks (256 rows each)
#define CNTB 512           // count blocks (side stream, grid-stride)
#define PADT 260           // padded row length of transposed x tile (even!)

typedef unsigned long long ull;

// ---------------- scratch (device globals; no allocation allowed) ----------
// +1 sentinel row everywhere: node NN is the "dead" pad target.
__device__ __align__(16) float g_xp1[(NN + 1) * 32];  // row NN: never written = 0
__device__ float g_as1[(NN + 1) * 4];  // slot NN*4..+3 = -1e30 (set by alloc)
__device__ float g_ad1[NN * 4];
__device__ __align__(16) float g_xp2[(NN + 1) * 8];   // row NN: zeros
__device__ float g_as2[NN + 1];        // slot NN = -1e30 (set by alloc)
__device__ float g_ad2[NN];
__device__ int   g_deg[NN];        // zero-init; reset to 0 by alloc each run
__device__ int   g_degP[NN];       // PADDED degree (multiple of 8)
__device__ int   g_off[NN];
__device__ int   g_pos[NN];
__device__ __align__(8) int g_csr[NEMAX];
__device__ int   g_total;          // zero-init; reset to 0 by scatter each run

// ---------------- packed f32x2 helpers ------------------------------------
__device__ __forceinline__ ull dup2(float v) {
    ull r; unsigned u = __float_as_uint(v);
    asm("mov.b64 %0, {%1, %1};" : "=l"(r) : "r"(u));
    return r;
}
__device__ __forceinline__ ull fma2(ull a, ull b, ull c) {
    ull d;
    asm("fma.rn.f32x2 %0, %1, %2, %3;" : "=l"(d) : "l"(a), "l"(b), "l"(c));
    return d;
}
__device__ __forceinline__ void unpack2(ull v, float& lo, float& hi) {
    unsigned a, b;
    asm("mov.b64 {%0, %1}, %2;" : "=r"(a), "=r"(b) : "l"(v));
    lo = __uint_as_float(a); hi = __uint_as_float(b);
}

// ============ K1: GEMM1 + fused attn1 epilogue (main stream) ===============
__global__ __launch_bounds__(256) void k1_gemm(
    const float* __restrict__ x, const float* __restrict__ W,
    const float* __restrict__ as1, const float* __restrict__ ad1)
{
    __shared__ float xs[32 * PADT];            // [k][row] transposed
    __shared__ float ws[32 * 32];              // [k][col]
    int t = threadIdx.x;
    int row0 = blockIdx.x * 256;
    int rg  = t >> 3;                          // 0..31 -> rows rg*8..rg*8+7
    int cg4 = (t & 7) << 2;                    // 0,4,...,28 col base

    ull acc[4][4];
#pragma unroll
    for (int p = 0; p < 4; p++)
#pragma unroll
        for (int c = 0; c < 4; c++) acc[p][c] = 0ull;

    for (int kk = 0; kk < 512; kk += 32) {
#pragma unroll
        for (int i = 0; i < 8; i++) {
            int lf  = i * 256 + t;
            int row = lf >> 3;
            int k4  = (lf & 7) << 2;
            float4 v = make_float4(0.f, 0.f, 0.f, 0.f);
            int grow = row0 + row;
            if (grow < NN)
                v = *(const float4*)(x + (size_t)grow * 512 + kk + k4);
            xs[(k4 + 0) * PADT + row] = v.x;
            xs[(k4 + 1) * PADT + row] = v.y;
            xs[(k4 + 2) * PADT + row] = v.z;
            xs[(k4 + 3) * PADT + row] = v.w;
        }
        {
            int r = t >> 3, k4 = (t & 7) << 2;
            *(float4*)&ws[r * 32 + k4] = *(const float4*)(W + (size_t)(kk + r) * 32 + k4);
        }
        __syncthreads();
#pragma unroll
        for (int k = 0; k < 32; k++) {
            float4 wv = *(float4*)&ws[k * 32 + cg4];
            ull w0 = dup2(wv.x), w1 = dup2(wv.y), w2 = dup2(wv.z), w3 = dup2(wv.w);
            const ull* xr = (const ull*)&xs[k * PADT + (rg << 3)];
            ull x0 = xr[0], x1 = xr[1], x2 = xr[2], x3 = xr[3];
            acc[0][0] = fma2(x0, w0, acc[0][0]); acc[0][1] = fma2(x0, w1, acc[0][1]);
            acc[0][2] = fma2(x0, w2, acc[0][2]); acc[0][3] = fma2(x0, w3, acc[0][3]);
            acc[1][0] = fma2(x1, w0, acc[1][0]); acc[1][1] = fma2(x1, w1, acc[1][1]);
            acc[1][2] = fma2(x1, w2, acc[1][2]); acc[1][3] = fma2(x1, w3, acc[1][3]);
            acc[2][0] = fma2(x2, w0, acc[2][0]); acc[2][1] = fma2(x2, w1, acc[2][1]);
            acc[2][2] = fma2(x2, w2, acc[2][2]); acc[2][3] = fma2(x2, w3, acc[2][3]);
            acc[3][0] = fma2(x3, w0, acc[3][0]); acc[3][1] = fma2(x3, w1, acc[3][1]);
            acc[3][2] = fma2(x3, w2, acc[3][2]); acc[3][3] = fma2(x3, w3, acc[3][3]);
        }
        __syncthreads();
    }

    int head = cg4 >> 3;
    int half = (cg4 >> 2) & 1;
    float a_s[4], a_d[4];
#pragma unroll
    for (int c = 0; c < 4; c++) {
        a_s[c] = as1[head * 8 + half * 4 + c];
        a_d[c] = ad1[head * 8 + half * 4 + c];
    }
#pragma unroll
    for (int p = 0; p < 4; p++) {
        float o0[4], o1[4];
#pragma unroll
        for (int c = 0; c < 4; c++) unpack2(acc[p][c], o0[c], o1[c]);
#pragma unroll
        for (int rr = 0; rr < 2; rr++) {
            float* o = rr ? o1 : o0;
            int row = row0 + (rg << 3) + (p << 1) + rr;
            float sv = o[0]*a_s[0] + o[1]*a_s[1] + o[2]*a_s[2] + o[3]*a_s[3];
            float dv = o[0]*a_d[0] + o[1]*a_d[1] + o[2]*a_d[2] + o[3]*a_d[3];
            sv += __shfl_xor_sync(0xffffffffu, sv, 1);
            dv += __shfl_xor_sync(0xffffffffu, dv, 1);
            if (row < NN) {
                *(float4*)(g_xp1 + (size_t)row * 32 + cg4) =
                    make_float4(o[0], o[1], o[2], o[3]);
                if (half == 0) g_as1[row * 4 + head] = sv;
                else           g_ad1[row * 4 + head] = dv;
            }
        }
    }
}

// ---------------- degree count (side stream) -------------------------------
__global__ void count_kernel(const int* __restrict__ dst, int E) {
    int i = blockIdx.x * blockDim.x + threadIdx.x;
    for (; i < E; i += CNTB * 256) atomicAdd(&g_deg[dst[i]], 1);
}

// ------ CSR alloc: pad segments to 8 with sentinel NN; reset g_deg ---------
__global__ void alloc_kernel() {
    int n = blockIdx.x * blockDim.x + threadIdx.x;
    int lane = threadIdx.x & 31;
    int deg = (n < NN) ? g_deg[n] + 1 : 0;     // +1 self-loop
    int degP = (deg + 7) & ~7;                 // padded
    int scan = degP;
#pragma unroll
    for (int d = 1; d < 32; d <<= 1) {
        int tv = __shfl_up_sync(0xffffffffu, scan, d);
        if (lane >= d) scan += tv;
    }
    int total = __shfl_sync(0xffffffffu, scan, 31);
    int base = 0;
    if (lane == 31) base = atomicAdd(&g_total, total);
    base = __shfl_sync(0xffffffffu, base, 31);
    int off = base + scan - degP;
    if (n == 0) {                              // sentinel attention = -inf-ish
        g_as1[NN * 4 + 0] = -1e30f; g_as1[NN * 4 + 1] = -1e30f;
        g_as1[NN * 4 + 2] = -1e30f; g_as1[NN * 4 + 3] = -1e30f;
        g_as2[NN] = -1e30f;
    }
    if (n < NN) {
        g_off[n]  = off;
        g_csr[off] = n;                        // self-loop in slot 0
        g_pos[n]  = off + 1;
        g_degP[n] = degP;
        for (int i = deg; i < degP; i++) g_csr[off + i] = NN;  // sentinel pads
        g_deg[n]  = 0;                          // ready for next replay
    }
}

__global__ void scatter_kernel(const int* __restrict__ src,
                               const int* __restrict__ dst, int E) {
    if (blockIdx.x == 0 && threadIdx.x == 0) g_total = 0;
    int i = blockIdx.x * blockDim.x + threadIdx.x;
    if (i >= E) return;
    int d = dst[i];
    int slot = atomicAdd(&g_pos[d], 1);
    g_csr[slot] = src[i];
}

// == l1: zero-shuffle, predicate-free hot loop, fused ELU + xp2/as2/ad2 =====
__global__ __launch_bounds__(256) void l1_kernel(
    const float* __restrict__ b1, const float* __restrict__ W2,
    const float* __restrict__ as2v, const float* __restrict__ ad2v)
{
    __shared__ float W2s[256];
    __shared__ float hs[8][36];
    int t = threadIdx.x;
    W2s[t] = W2[t];
    __syncthreads();

    int wid = t >> 5, lane = t & 31;
    int n = blockIdx.x * 8 + wid;              // grid 12500*8 == NN exactly
    int off = g_off[n], degP = g_degP[n];
    int q  = lane >> 3;                        // edge-pair group 0..3
    int c4 = lane & 7;                         // channel quad (head = c4>>1)
    int hc = c4 >> 1;
    float adh = g_ad1[n * 4 + hc];
    const float* xp1q = g_xp1 + (c4 << 2);
    const int* csrp = g_csr + off + (q << 1);

    float4 acc = make_float4(0.f, 0.f, 0.f, 0.f);
    float sum = 0.f;
#pragma unroll 2
    for (int base = 0; base < degP; base += 8) {
        int2 s2 = *(const int2*)(csrp + base);  // edges 2q, 2q+1 (8-dup)
        float vA = g_as1[s2.x * 4 + hc] + adh;
        float vB = g_as1[s2.y * 4 + hc] + adh;
        vA = fmaxf(vA, 0.2f * vA);              // leaky relu
        vB = fmaxf(vB, 0.2f * vB);
        float pA = __expf(vA);                  // sentinel -> exp(-2e29) = 0
        float pB = __expf(vB);
        sum += pA + pB;
        float4 xa = *(const float4*)(xp1q + (size_t)s2.x * 32);
        float4 xb = *(const float4*)(xp1q + (size_t)s2.y * 32);
        acc.x = fmaf(pA, xa.x, fmaf(pB, xb.x, acc.x));
        acc.y = fmaf(pA, xa.y, fmaf(pB, xb.y, acc.y));
        acc.z = fmaf(pA, xa.z, fmaf(pB, xb.z, acc.z));
        acc.w = fmaf(pA, xa.w, fmaf(pB, xb.w, acc.w));
    }
    // reduce over edge-pair groups q (bits 3,4); sum lands per-head in-lane
    sum   += __shfl_xor_sync(0xffffffffu, sum, 8);
    acc.x += __shfl_xor_sync(0xffffffffu, acc.x, 8);
    acc.y += __shfl_xor_sync(0xffffffffu, acc.y, 8);
    acc.z += __shfl_xor_sync(0xffffffffu, acc.z, 8);
    acc.w += __shfl_xor_sync(0xffffffffu, acc.w, 8);
    sum   += __shfl_xor_sync(0xffffffffu, sum, 16);
    acc.x += __shfl_xor_sync(0xffffffffu, acc.x, 16);
    acc.y += __shfl_xor_sync(0xffffffffu, acc.y, 16);
    acc.z += __shfl_xor_sync(0xffffffffu, acc.z, 16);
    acc.w += __shfl_xor_sync(0xffffffffu, acc.w, 16);
    float invd = 1.f / sum;                     // already per-head, in-lane

    if (q == 0) {                               // lanes 0..7 hold all quads
        float4 bv = *(const float4*)(b1 + (c4 << 2));
        float o0 = fmaf(acc.x, invd, bv.x);
        float o1 = fmaf(acc.y, invd, bv.y);
        float o2 = fmaf(acc.z, invd, bv.z);
        float o3 = fmaf(acc.w, invd, bv.w);
        o0 = o0 > 0.f ? o0 : expm1f(o0);
        o1 = o1 > 0.f ? o1 : expm1f(o1);
        o2 = o2 > 0.f ? o2 : expm1f(o2);
        o3 = o3 > 0.f ? o3 : expm1f(o3);
        *(float4*)&hs[wid][c4 << 2] = make_float4(o0, o1, o2, o3);
    }
    __syncwarp();

    // fused xp2 = h @ W2, plus as2/ad2
    if (lane < 8) {
        float s2 = 0.f;
#pragma unroll
        for (int k2 = 0; k2 < 32; k2++)
            s2 = fmaf(hs[wid][k2], W2s[k2 * 8 + lane], s2);
        g_xp2[(size_t)n * 8 + lane] = s2;
        float a = s2 * as2v[lane], d = s2 * ad2v[lane];
        a += __shfl_xor_sync(0xffu, a, 1);
        a += __shfl_xor_sync(0xffu, a, 2);
        a += __shfl_xor_sync(0xffu, a, 4);
        d += __shfl_xor_sync(0xffu, d, 1);
        d += __shfl_xor_sync(0xffu, d, 2);
        d += __shfl_xor_sync(0xffu, d, 4);
        if (lane == 0) { g_as2[n] = a; g_ad2[n] = d; }
    }
}

// ========== l2: zero-shuffle, predicate-free hot loop ======================
__global__ __launch_bounds__(256) void l2_kernel(float* __restrict__ out,
                                                 const float* __restrict__ b2)
{
    int t = threadIdx.x, wid = t >> 5, lane = t & 31;
    int n = blockIdx.x * 8 + wid;
    int off = g_off[n], degP = g_degP[n];
    int j8 = lane >> 2, c2 = lane & 3;          // edge j8, channel-pair c2
    float adn = g_ad2[n];
    const float* xp2p = g_xp2 + (c2 << 1);

    float2 acc = make_float2(0.f, 0.f);
    float sum = 0.f;
#pragma unroll 2
    for (int base = 0; base < degP; base += 8) {
        int sv = g_csr[off + base + j8];         // 8 distinct, 4-way dup
        float v = g_as2[sv] + adn;
        v = fmaxf(v, 0.2f * v);
        float p = __expf(v);                      // sentinel -> 0
        sum += p;
        float2 xv = *(const float2*)(xp2p + (size_t)sv * 8);
        acc.x = fmaf(p, xv.x, acc.x);
        acc.y = fmaf(p, xv.y, acc.y);
    }
    // reduce over edge lanes j8 (bits 2,3,4)
    sum   += __shfl_xor_sync(0xffffffffu, sum, 4);
    acc.x += __shfl_xor_sync(0xffffffffu, acc.x, 4);
    acc.y += __shfl_xor_sync(0xffffffffu, acc.y, 4);
    sum   += __shfl_xor_sync(0xffffffffu, sum, 8);
    acc.x += __shfl_xor_sync(0xffffffffu, acc.x, 8);
    acc.y += __shfl_xor_sync(0xffffffffu, acc.y, 8);
    sum   += __shfl_xor_sync(0xffffffffu, sum, 16);
    acc.x += __shfl_xor_sync(0xffffffffu, acc.x, 16);
    acc.y += __shfl_xor_sync(0xffffffffu, acc.y, 16);
    float invd = 1.f / sum;
    if (lane < 4) {
        float2 bv = *(const float2*)(b2 + (c2 << 1));
        float2 ov;
        ov.x = fmaf(acc.x, invd, bv.x);
        ov.y = fmaf(acc.y, invd, bv.y);
        *(float2*)(out + (size_t)n * 8 + (c2 << 1)) = ov;
    }
}

// ---------------------------------------------------------------------------
extern "C" void kernel_launch(void* const* d_in, const int* in_sizes, int n_in,
                              void* d_out, int out_size) {
    const float* x        = (const float*)d_in[0];
    const int*   eidx     = (const int*)d_in[1];
    const float* W1       = (const float*)d_in[2];
    const float* att_src1 = (const float*)d_in[3];
    const float* att_dst1 = (const float*)d_in[4];
    const float* b1       = (const float*)d_in[5];
    const float* W2       = (const float*)d_in[6];
    const float* att_src2 = (const float*)d_in[7];
    const float* att_dst2 = (const float*)d_in[8];
    const float* b2       = (const float*)d_in[9];
    float* out = (float*)d_out;

    int E = in_sizes[1] / 2;
    const int* src = eidx;
    const int* dst = eidx + E;

    // lazy one-time stream/event setup (first call is the un-captured
    // correctness run; captured replays reuse the same handles)
    static cudaStream_t s2 = nullptr;
    static cudaEvent_t ev_root = nullptr, ev_csr = nullptr;
    if (s2 == nullptr) {
        cudaStreamCreateWithFlags(&s2, cudaStreamNonBlocking);
        cudaEventCreateWithFlags(&ev_root, cudaEventDisableTiming);
        cudaEventCreateWithFlags(&ev_csr, cudaEventDisableTiming);
    }

    // fork: CSR chain on s2, GEMM on the captured (default) stream
    cudaEventRecord(ev_root, 0);
    cudaStreamWaitEvent(s2, ev_root, 0);
    count_kernel<<<CNTB, 256, 0, s2>>>(dst, E);
    alloc_kernel<<<(NN + 255) / 256, 256, 0, s2>>>();
    scatter_kernel<<<(E + 255) / 256, 256, 0, s2>>>(src, dst, E);
    cudaEventRecord(ev_csr, s2);

    k1_gemm<<<GEMMB, 256>>>(x, W1, att_src1, att_dst1);

    // join, then the two attention layers
    cudaStreamWaitEvent(0, ev_csr, 0);
    l1_kernel<<<NN / 8, 256>>>(b1, W2, att_src2, att_dst2);
    l2_kernel<<<NN / 8, 256>>>(out, b2);
}